// round 14
// baseline (speedup 1.0000x reference)
#include <cuda_runtime.h>

#define NDIM 128
#define PLANE 16384          // 128*128
#define CS 2097152           // 128^3 (channel stride)
#define TVX 32               // tile voxels in x (2 per thread)
#define TVY 8
#define ZC 16
#define ROWL 36              // TVX+2 = 34, padded to 36
#define COLH 10              // TVY+2
#define NSLOT (ROWL*COLH)    // 360 per volume
#define VSTR 368             // smem stride between volumes (==16 mod 32)
#define TOTSLOT (2*NSLOT)    // 720
#define NTHREADS 256
#define NBLOCKS 1024         // 4 * 16 * 16

__device__ double g_acc;          // zero-init at load; self-resetting
__device__ unsigned int g_cnt;    // ditto

// 2-voxel computeH: halo window rows base..base+2, cols 0..3 relative.
__device__ __forceinline__ void computeH2(const float* __restrict__ sm,
                                          int base, float* H0, float* H1) {
    const float* r0 = sm + base;
    const float* r1 = r0 + ROWL;
    const float* r2 = r1 + ROWL;
    float2 p00 = *(const float2*)(r0), p01 = *(const float2*)(r0 + 2);
    float2 p10 = *(const float2*)(r1), p11 = *(const float2*)(r1 + 2);
    float2 p20 = *(const float2*)(r2), p21 = *(const float2*)(r2 + 2);
    float a0[4] = {p00.x, p00.y, p01.x, p01.y};
    float a1[4] = {p10.x, p10.y, p11.x, p11.y};
    float a2[4] = {p20.x, p20.y, p21.x, p21.y};
    float sc[4], dc[4], oc[4];
    #pragma unroll
    for (int c = 0; c < 4; c++) {
        float t = a0[c] + a2[c];
        sc[c] = fmaf(2.f, a1[c], t);
        oc[c] = t + a1[c];
        dc[c] = a2[c] - a0[c];
    }
    {
        float ts = sc[0] + sc[2], td = dc[0] + dc[2], to = oc[0] + oc[2];
        H0[0] = sc[2] - sc[0];
        H0[1] = fmaf(2.f, dc[1], td);
        H0[2] = oc[2] - oc[0];
        H0[3] = td + dc[1];
        H0[4] = fmaf(2.f, sc[1], ts);
        H0[5] = fmaf(2.f, oc[1], to);
        H0[6] = ts + sc[1];
    }
    {
        float ts = sc[1] + sc[3], td = dc[1] + dc[3], to = oc[1] + oc[3];
        H1[0] = sc[3] - sc[1];
        H1[1] = fmaf(2.f, dc[2], td);
        H1[2] = oc[3] - oc[1];
        H1[3] = td + dc[2];
        H1[4] = fmaf(2.f, sc[2], ts);
        H1[5] = fmaf(2.f, oc[2], to);
        H1[6] = ts + sc[2];
    }
}

// Combine z-ring (A=z-1, B=z, C=z+1) into edge magnitude * 0.5.
__device__ __forceinline__ float edgeFromH(const float* A, const float* B, const float* C) {
    float t;
    t = A[0] + C[0];
    float Gssd = fmaf(2.f, B[0], t);
    float Gosd = t + B[0];
    t = A[1] + C[1];
    float Gsds = fmaf(2.f, B[1], t);
    float Gods = t + B[1];
    t = A[2] + C[2];
    float Gsod = fmaf(2.f, B[2], t);
    t = A[3] + C[3];
    float Gsdo = fmaf(2.f, B[3], t);
    float Gdss = C[4] - A[4];
    float Gdos = C[5] - A[5];
    float Gdso = C[6] - A[6];
    float s1 = Gssd * Gssd;
    s1 = fmaf(Gsds, Gsds, s1);
    s1 = fmaf(Gdss, Gdss, s1);
    float s2 = Gsod * Gsod;
    s2 = fmaf(Gsdo, Gsdo, s2);
    s2 = fmaf(Gosd, Gosd, s2);
    s2 = fmaf(Gods, Gods, s2);
    s2 = fmaf(Gdso, Gdso, s2);
    s2 = fmaf(Gdos, Gdos, s2);
    float s = fmaf(2.f, s2, s1) + 1e-12f;
    float r;
    asm("sqrt.approx.f32 %0, %1;" : "=f"(r) : "f"(s));
    return 0.5f * r;
}

__global__ __launch_bounds__(NTHREADS, 3)
void gme_kernel(const float* __restrict__ Y, const float* __restrict__ P,
                float* __restrict__ out, int out_n) {
    __shared__ float sm0[2 * VSTR];
    __shared__ float sm1[2 * VSTR];
    __shared__ float wsum[NTHREADS / 32];

    int lane = threadIdx.x;            // 0..31
    int ty = threadIdx.y;              // 0..7
    int tid = ty * 32 + lane;
    int vol = lane >> 4;               // 0 = Y, 1 = P
    int lx = lane & 15;                // voxel-pair: x = x0 + 2*lx, +1
    int x0 = blockIdx.x * TVX;
    int y0 = blockIdx.y * TVY;
    int zb = blockIdx.z;
    int b = zb >> 3;                   // 8 z-chunks per batch
    int z0 = (zb & 7) * ZC;
    const float* Yb = Y + (long)b * 2 * CS;
    const float* Pb = P + (long)b * 2 * CS;

    // ---- plane-invariant halo addressing: 3 loader slots/thread ----
#define SLOTSETUP(T, bp, mm, si) {                                     \
        int _t = (T);                                                  \
        int _v = (_t >= NSLOT) ? 1 : 0;                                \
        int _r = _t - _v * NSLOT;                                      \
        int _yy = _r / ROWL, _xx = _r - _yy * ROWL;                    \
        int _gy = y0 + _yy - 1, _gx = x0 + _xx - 1;                    \
        mm = (_xx < 34) && ((unsigned)_gy < NDIM) && ((unsigned)_gx < NDIM); \
        bp = (_v ? Pb : Yb) + (mm ? _gy * NDIM + _gx : 0);             \
        si = _v * VSTR + _r;                                           \
    }
    const float *bpA, *bpB, *bpC;
    bool mA, mB, mC;
    int siA, siB, siC;
    SLOTSETUP(tid, bpA, mA, siA);
    SLOTSETUP(tid + 256, bpB, mB, siB);
    bool hasC = (tid < TOTSLOT - 512);          // tid < 208
    {
        int tC = hasC ? (tid + 512) : 0;
        SLOTSETUP(tC, bpC, mC, siC);
        mC = mC && hasC;
    }
#undef SLOTSETUP

    int hbase = vol * VSTR + ty * ROWL + 2 * lx;   // computeH2 anchor

    float rA, rB, rC;

#define PREF(zz) do {                                              \
        int _z = (zz);                                             \
        bool zin = ((unsigned)_z < NDIM);                          \
        int zoff = _z * PLANE;                                     \
        rA = 0.f; rB = 0.f; rC = 0.f;                              \
        if (zin & mA) rA = bpA[zoff] + bpA[zoff + CS];             \
        if (zin & mB) rB = bpB[zoff] + bpB[zoff + CS];             \
        if (zin & mC) rC = bpC[zoff] + bpC[zoff + CS];             \
    } while (0)

    float *cS = sm0, *nS = sm1;

#define EMIT(A, B, C) do {                                         \
        float e0 = edgeFromH(A, B, C);                             \
        float e1 = edgeFromH((A) + 7, (B) + 7, (C) + 7);           \
        float f0 = __shfl_xor_sync(0xffffffffu, e0, 16);           \
        float f1 = __shfl_xor_sync(0xffffffffu, e1, 16);           \
        float d0 = e0 - f0, d1 = e1 - f1;                          \
        acc = fmaf(d0, d0, acc);                                   \
        acc = fmaf(d1, d1, acc);                                   \
    } while (0)

    // Emit-lag-1 step: commit prefetched plane, barrier, issue next LDGs,
    // then do the PREVIOUS step's emit (reg-only; covers LDG+LDS latency),
    // then compute H for the just-committed plane (consumed next step).
#define STEPN(HH, zpre, DO_PF) do {                                \
        nS[siA] = rA;                                              \
        nS[siB] = rB;                                              \
        if (hasC) nS[siC] = rC;                                    \
        __syncthreads();                                           \
        { float* t = cS; cS = nS; nS = t; }                        \
        if (DO_PF) PREF(zpre);                                     \
        computeH2(cS, hbase, HH, (HH) + 7);                        \
    } while (0)

#define STEPE(HH, EA, EB, EC, zpre, DO_PF) do {                    \
        nS[siA] = rA;                                              \
        nS[siB] = rB;                                              \
        if (hasC) nS[siC] = rC;                                    \
        __syncthreads();                                           \
        { float* t = cS; cS = nS; nS = t; }                        \
        if (DO_PF) PREF(zpre);                                     \
        EMIT(EA, EB, EC);                                          \
        computeH2(cS, hbase, HH, (HH) + 7);                        \
    } while (0)

    float HA[14], HB[14], HC[14];
    float acc = 0.f;

    // prime: planes z0-1, z0, z0+1 -> HA, HB, HC
    PREF(z0 - 1);
    STEPN(HA, z0, 1);
    STEPN(HB, z0 + 1, 1);
    STEPN(HC, z0 + 2, 1);
    int zz = z0 + 3;
    // 15 emit+load steps (planes z0+2..z0+16, outputs z0..z0+14): 4x3 + 3 tail
    #pragma unroll 1
    for (int k = 0; k < 4; k++) {
        STEPE(HA, HA, HB, HC, zz, 1); zz++;
        STEPE(HB, HB, HC, HA, zz, 1); zz++;
        STEPE(HC, HC, HA, HB, zz, 1); zz++;
    }
    STEPE(HA, HA, HB, HC, zz, 1); zz++;
    STEPE(HB, HB, HC, HA, zz, 1);
    STEPE(HC, HC, HA, HB, 0, 0);
    // final emit-only: output z0+15 = (H(z0+14), H(z0+15), H(z0+16))
    EMIT(HA, HB, HC);

#undef STEPN
#undef STEPE
#undef EMIT
#undef PREF

    // block reduction (each voxel counted once per half-warp -> x2; fixed in mean)
    #pragma unroll
    for (int o = 16; o; o >>= 1)
        acc += __shfl_down_sync(0xffffffffu, acc, o);
    int l32 = tid & 31, wid = tid >> 5;
    if (l32 == 0) wsum[wid] = acc;
    __syncthreads();
    if (wid == 0) {
        float v = (l32 < NTHREADS / 32) ? wsum[l32] : 0.f;
        #pragma unroll
        for (int o = 4; o; o >>= 1)
            v += __shfl_down_sync(0xffffffffu, v, o);
        if (l32 == 0) {
            atomicAdd(&g_acc, (double)v);
            __threadfence();
            unsigned done = atomicAdd(&g_cnt, 1u);
            if (done == NBLOCKS - 1) {
                // mean over 2*128^3 outputs, /2 for the double count
                float m = (float)(g_acc / 8388608.0);
                for (int i = 0; i < out_n; i++) out[i] = m;
                g_acc = 0.0;
                __threadfence();
                g_cnt = 0u;
            }
        }
    }
}

extern "C" void kernel_launch(void* const* d_in, const int* in_sizes, int n_in,
                              void* d_out, int out_size) {
    const float* Y = (const float*)d_in[0];
    const float* P = (const float*)d_in[1];
    dim3 grid(NDIM / TVX, NDIM / TVY, (NDIM / ZC) * 2);  // 4 x 16 x 16 = 1024
    dim3 blk(32, 8);
    gme_kernel<<<grid, blk>>>(Y, P, (float*)d_out, out_size);
}

// round 15
// speedup vs baseline: 1.4553x; 1.4553x over previous
#include <cuda_runtime.h>

#define NDIM 128
#define PLANE 16384          // 128*128
#define CS 2097152           // 128^3 (channel stride)
#define TVX 32               // tile voxels in x (2 per thread)
#define TVY 8
#define ZC 16
#define ROWL 36              // 34 used cols + col34 extra + col35 dump
#define COLH 10              // TVY+2
#define F2ROW 18             // float2 slots per row
#define NF2 (F2ROW*COLH)     // 180 float2-slots per volume
#define VSTR 368             // float stride between volumes (==16 mod 32)
#define TOTF2 (2*NF2)        // 360
#define NTHREADS 256
#define NBLOCKS 1024         // 4 * 16 * 16

__device__ double g_acc;          // zero-init at load; self-resetting
__device__ unsigned int g_cnt;    // ditto

// 2-voxel computeH: halo window rows base..base+2, cols 0..3 relative.
// s=[1,2,1], d=[-1,0,1], o=[1,1,1]
// H[0]=s_y d_x  H[1]=d_y s_x  H[2]=o_y d_x  H[3]=d_y o_x
// H[4]=s_y s_x  H[5]=o_y s_x  H[6]=s_y o_x
__device__ __forceinline__ void computeH2(const float* __restrict__ sm,
                                          int base, float* H0, float* H1) {
    const float* r0 = sm + base;
    const float* r1 = r0 + ROWL;
    const float* r2 = r1 + ROWL;
    float2 p00 = *(const float2*)(r0), p01 = *(const float2*)(r0 + 2);
    float2 p10 = *(const float2*)(r1), p11 = *(const float2*)(r1 + 2);
    float2 p20 = *(const float2*)(r2), p21 = *(const float2*)(r2 + 2);
    float a0[4] = {p00.x, p00.y, p01.x, p01.y};
    float a1[4] = {p10.x, p10.y, p11.x, p11.y};
    float a2[4] = {p20.x, p20.y, p21.x, p21.y};
    float sc[4], dc[4], oc[4];
    #pragma unroll
    for (int c = 0; c < 4; c++) {
        float t = a0[c] + a2[c];
        sc[c] = fmaf(2.f, a1[c], t);
        oc[c] = t + a1[c];
        dc[c] = a2[c] - a0[c];
    }
    {
        float ts = sc[0] + sc[2], td = dc[0] + dc[2], to = oc[0] + oc[2];
        H0[0] = sc[2] - sc[0];
        H0[1] = fmaf(2.f, dc[1], td);
        H0[2] = oc[2] - oc[0];
        H0[3] = td + dc[1];
        H0[4] = fmaf(2.f, sc[1], ts);
        H0[5] = fmaf(2.f, oc[1], to);
        H0[6] = ts + sc[1];
    }
    {
        float ts = sc[1] + sc[3], td = dc[1] + dc[3], to = oc[1] + oc[3];
        H1[0] = sc[3] - sc[1];
        H1[1] = fmaf(2.f, dc[2], td);
        H1[2] = oc[3] - oc[1];
        H1[3] = td + dc[2];
        H1[4] = fmaf(2.f, sc[2], ts);
        H1[5] = fmaf(2.f, oc[2], to);
        H1[6] = ts + sc[2];
    }
}

// Combine z-ring (A=z-1, B=z, C=z+1) into edge magnitude * 0.5.
__device__ __forceinline__ float edgeFromH(const float* A, const float* B, const float* C) {
    float t;
    t = A[0] + C[0];
    float Gssd = fmaf(2.f, B[0], t);
    float Gosd = t + B[0];
    t = A[1] + C[1];
    float Gsds = fmaf(2.f, B[1], t);
    float Gods = t + B[1];
    t = A[2] + C[2];
    float Gsod = fmaf(2.f, B[2], t);
    t = A[3] + C[3];
    float Gsdo = fmaf(2.f, B[3], t);
    float Gdss = C[4] - A[4];
    float Gdos = C[5] - A[5];
    float Gdso = C[6] - A[6];
    float s1 = Gssd * Gssd;
    s1 = fmaf(Gsds, Gsds, s1);
    s1 = fmaf(Gdss, Gdss, s1);
    float s2 = Gsod * Gsod;
    s2 = fmaf(Gsdo, Gsdo, s2);
    s2 = fmaf(Gosd, Gosd, s2);
    s2 = fmaf(Gods, Gods, s2);
    s2 = fmaf(Gdso, Gdso, s2);
    s2 = fmaf(Gdos, Gdos, s2);
    float s = fmaf(2.f, s2, s1) + 1e-12f;
    float r;
    asm("sqrt.approx.f32 %0, %1;" : "=f"(r) : "f"(s));
    return 0.5f * r;
}

__global__ __launch_bounds__(NTHREADS, 3)
void gme_kernel(const float* __restrict__ Y, const float* __restrict__ P,
                float* __restrict__ out, int out_n) {
    __shared__ float sm0[2 * VSTR];
    __shared__ float sm1[2 * VSTR];
    __shared__ float wsum[NTHREADS / 32];

    int lane = threadIdx.x;            // 0..31
    int ty = threadIdx.y;              // 0..7
    int tid = ty * 32 + lane;
    int vol = lane >> 4;               // 0 = Y, 1 = P
    int lx = lane & 15;                // voxel-pair: x = x0 + 2*lx, +1
    int x0 = blockIdx.x * TVX;
    int y0 = blockIdx.y * TVY;
    int zb = blockIdx.z;
    int b = zb >> 3;                   // 8 z-chunks per batch
    int z0 = (zb & 7) * ZC;
    const float* Yb = Y + (long)b * 2 * CS;
    const float* Pb = P + (long)b * 2 * CS;

    // ---- plane-invariant halo addressing: 2 float2 loader slots/thread ----
    // slot covers float2 t over [0, 360): v = t>=180, row = r/18, j = r%18.
    // Global pair (gxlo, gxlo+1) = (x0-2+2j, x0-1+2j); smem cols (2j-1, 2j)
    // relative layout col c <-> gx = x0-1+c. j=0 lo goes to dump col 35.
#define SLOTSETUP(T, bp, mm, siHi, siLo) {                                 \
        int _t = (T);                                                      \
        int _v = (_t >= NF2) ? 1 : 0;                                      \
        int _r = _t - _v * NF2;                                            \
        int _row = _r / F2ROW, _j = _r - _row * F2ROW;                     \
        int _gy = y0 + _row - 1, _gx = x0 - 2 + 2 * _j;                    \
        mm = ((unsigned)_gy < NDIM) && ((unsigned)_gx < NDIM);             \
        bp = (_v ? Pb : Yb) + (mm ? _gy * NDIM + _gx : 0);                 \
        siHi = _v * VSTR + _row * ROWL + 2 * _j;                           \
        siLo = (_j > 0) ? (siHi - 1) : (_v * VSTR + _row * ROWL + 35);     \
    }
    const float *bpA, *bpB;
    bool mA, mB;
    int siAH, siAL, siBH, siBL;
    SLOTSETUP(tid, bpA, mA, siAH, siAL);
    bool hasB = (tid < TOTF2 - NTHREADS);          // tid < 104
    {
        int tB = hasB ? (tid + NTHREADS) : 0;
        SLOTSETUP(tB, bpB, mB, siBH, siBL);
        mB = mB && hasB;
    }
#undef SLOTSETUP

    int hbase = vol * VSTR + ty * ROWL + 2 * lx;   // computeH2 anchor

    float2 rA, rB;

#define PREF(zz) do {                                              \
        int _z = (zz);                                             \
        bool zin = ((unsigned)_z < NDIM);                          \
        int zoff = _z * PLANE;                                     \
        rA = make_float2(0.f, 0.f);                                \
        rB = make_float2(0.f, 0.f);                                \
        if (zin & mA) {                                            \
            float2 c0 = *(const float2*)(bpA + zoff);              \
            float2 c1 = *(const float2*)(bpA + zoff + CS);         \
            rA.x = c0.x + c1.x; rA.y = c0.y + c1.y;                \
        }                                                          \
        if (zin & mB) {                                            \
            float2 c0 = *(const float2*)(bpB + zoff);              \
            float2 c1 = *(const float2*)(bpB + zoff + CS);         \
            rB.x = c0.x + c1.x; rB.y = c0.y + c1.y;                \
        }                                                          \
    } while (0)

    float *cS = sm0, *nS = sm1;

#define STEP(HH, zpre, DO_PF) do {                                 \
        nS[siAH] = rA.y; nS[siAL] = rA.x;                          \
        if (hasB) { nS[siBH] = rB.y; nS[siBL] = rB.x; }            \
        __syncthreads();                                           \
        { float* t = cS; cS = nS; nS = t; }                        \
        if (DO_PF) PREF(zpre);                                     \
        computeH2(cS, hbase, HH, (HH) + 7);                        \
    } while (0)

#define EMIT(A, B, C) do {                                         \
        float e0 = edgeFromH(A, B, C);                             \
        float e1 = edgeFromH((A) + 7, (B) + 7, (C) + 7);           \
        float f0 = __shfl_xor_sync(0xffffffffu, e0, 16);           \
        float f1 = __shfl_xor_sync(0xffffffffu, e1, 16);           \
        float d0 = e0 - f0, d1 = e1 - f1;                          \
        acc = fmaf(d0, d0, acc);                                   \
        acc = fmaf(d1, d1, acc);                                   \
    } while (0)

    float HA[14], HB[14], HC[14];
    float acc = 0.f;

    PREF(z0 - 1);
    STEP(HA, z0, 1);
    STEP(HB, z0 + 1, 1);
    int zz = z0 + 2;
    // 16 emit-steps: 5 x 3 + 1 tail  (18 planes total for ZC=16)
    #pragma unroll 1
    for (int k = 0; k < 5; k++) {
        STEP(HC, zz, 1); EMIT(HA, HB, HC); zz++;
        STEP(HA, zz, 1); EMIT(HB, HC, HA); zz++;
        STEP(HB, zz, 1); EMIT(HC, HA, HB); zz++;
    }
    STEP(HC, 0, 0); EMIT(HA, HB, HC);

#undef STEP
#undef EMIT
#undef PREF

    // block reduction (each voxel counted once per half-warp -> x2; fixed in mean)
    #pragma unroll
    for (int o = 16; o; o >>= 1)
        acc += __shfl_down_sync(0xffffffffu, acc, o);
    int l32 = tid & 31, wid = tid >> 5;
    if (l32 == 0) wsum[wid] = acc;
    __syncthreads();
    if (wid == 0) {
        float v = (l32 < NTHREADS / 32) ? wsum[l32] : 0.f;
        #pragma unroll
        for (int o = 4; o; o >>= 1)
            v += __shfl_down_sync(0xffffffffu, v, o);
        if (l32 == 0) {
            atomicAdd(&g_acc, (double)v);
            __threadfence();
            unsigned done = atomicAdd(&g_cnt, 1u);
            if (done == NBLOCKS - 1) {
                // mean over 2*128^3 outputs, /2 for the double count
                float m = (float)(g_acc / 8388608.0);
                for (int i = 0; i < out_n; i++) out[i] = m;
                g_acc = 0.0;
                __threadfence();
                g_cnt = 0u;
            }
        }
    }
}

extern "C" void kernel_launch(void* const* d_in, const int* in_sizes, int n_in,
                              void* d_out, int out_size) {
    const float* Y = (const float*)d_in[0];
    const float* P = (const float*)d_in[1];
    dim3 grid(NDIM / TVX, NDIM / TVY, (NDIM / ZC) * 2);  // 4 x 16 x 16 = 1024
    dim3 blk(32, 8);
    gme_kernel<<<grid, blk>>>(Y, P, (float*)d_out, out_size);
}